// round 5
// baseline (speedup 1.0000x reference)
#include <cuda_runtime.h>
#include <math.h>
#include <mma.h>

using namespace nvcuda;

#define BSZ     4
#define LSEQ    4096
#define DMODEL  768
#define DSTATE  128
#define HEADDIM 64
#define DINNER  1536
#define NHEADS  24
#define DPROJ   3352       // logical in-proj width
#define DPROJP  3456       // padded to 27*128
#define CONVCH  1792       // 1536 + 2*128
#define EPSV    1e-5f
#define NBT     (BSZ*LSEQ) // 16384
#define TCH     32         // scan chunk (timesteps staged in smem)

typedef unsigned long long u64;

// ---------------- scratch (static device globals) ---------------------------
__device__ float g_u   [(size_t)NBT * DMODEL];
__device__ float g_zx  [(size_t)NBT * DPROJP];
__device__ float g_xbc [(size_t)NBT * CONVCH];
__device__ float g_y   [(size_t)NBT * DINNER];
__device__ float g_dA  [NBT * NHEADS];
__device__ float g_dt  [NBT * NHEADS];
__device__ float g_win [(size_t)DMODEL * DPROJP];   // tf32, padded
__device__ float g_wout[(size_t)DINNER * DMODEL];   // tf32

// ---------------- small asm helpers -----------------------------------------
__device__ __forceinline__ float to_tf32(float x) {
    float r; asm("cvt.rna.tf32.f32 %0, %1;" : "=f"(r) : "f"(x)); return r;
}
__device__ __forceinline__ u64 pk2(float lo, float hi) {
    u64 d; asm("mov.b64 %0, {%1, %2};" : "=l"(d) : "f"(lo), "f"(hi)); return d;
}
__device__ __forceinline__ void up2(u64 v, float& lo, float& hi) {
    asm("mov.b64 {%0, %1}, %2;" : "=f"(lo), "=f"(hi) : "l"(v));
}
__device__ __forceinline__ u64 ffma2(u64 a, u64 b, u64 c) {
    u64 d; asm("fma.rn.f32x2 %0, %1, %2, %3;" : "=l"(d) : "l"(a), "l"(b), "l"(c)); return d;
}
__device__ __forceinline__ u64 fmul2(u64 a, u64 b) {
    u64 d; asm("mul.rn.f32x2 %0, %1, %2;" : "=l"(d) : "l"(a), "l"(b)); return d;
}
__device__ __forceinline__ unsigned smem_u32(const void* p) {
    return (unsigned)__cvta_generic_to_shared(p);
}
#define CP16(dst, src)  asm volatile("cp.async.cg.shared.global [%0], [%1], 16;" :: "r"(dst), "l"(src))
#define CP_COMMIT()     asm volatile("cp.async.commit_group;")
#define CP_WAIT(n)      asm volatile("cp.async.wait_group %0;" :: "n"(n))

__device__ __forceinline__ float block_reduce_sum(float v, float* red) {
    #pragma unroll
    for (int o = 16; o; o >>= 1) v += __shfl_down_sync(0xffffffffu, v, o);
    int lane = threadIdx.x & 31, wid = threadIdx.x >> 5;
    if (lane == 0) red[wid] = v;
    __syncthreads();
    int nw = blockDim.x >> 5;
    v = (threadIdx.x < nw) ? red[threadIdx.x] : 0.f;
    if (wid == 0) {
        #pragma unroll
        for (int o = 16; o; o >>= 1) v += __shfl_down_sync(0xffffffffu, v, o);
        if (lane == 0) red[0] = v;
    }
    __syncthreads();
    return red[0];
}

// ---------------- 0) weight convert/pad (tf32) ------------------------------
__global__ void cvt_win_kernel(const float* __restrict__ W) {
    int idx = blockIdx.x * 256 + threadIdx.x;
    if (idx >= DMODEL * DPROJP) return;
    int r = idx / DPROJP, c = idx % DPROJP;
    g_win[idx] = (c < DPROJ) ? to_tf32(W[(size_t)r * DPROJ + c]) : 0.f;
}
__global__ void cvt_wout_kernel(const float* __restrict__ W) {
    int idx = blockIdx.x * 256 + threadIdx.x;
    if (idx < DINNER * DMODEL) g_wout[idx] = to_tf32(W[idx]);
}

// ---------------- 1) LayerNorm (emits tf32-rounded u) -----------------------
__global__ void __launch_bounds__(256) ln_kernel(const float* __restrict__ x,
                                                 const float* __restrict__ w,
                                                 const float* __restrict__ b) {
    __shared__ float red[32];
    int row = blockIdx.x;
    const float* xr = x + (size_t)row * DMODEL;
    float v[3], s = 0.f, ss = 0.f;
    #pragma unroll
    for (int i = 0; i < 3; i++) {
        v[i] = xr[threadIdx.x + i * 256];
        s += v[i]; ss += v[i] * v[i];
    }
    float tot = block_reduce_sum(s, red);
    __syncthreads();
    float tot2 = block_reduce_sum(ss, red);
    float mu  = tot / DMODEL;
    float var = tot2 / DMODEL - mu * mu;
    float inv = rsqrtf(var + EPSV);
    float* ur = g_u + (size_t)row * DMODEL;
    #pragma unroll
    for (int i = 0; i < 3; i++) {
        int c = threadIdx.x + i * 256;
        ur[c] = to_tf32((v[i] - mu) * inv * w[c] + b[c]);
    }
}

// ---------------- TF32 tensor GEMM, cp.async double-buffered ----------------
// 128x128 tile, BK=16, 2 stages. A [M,K] row-major (already tf32-rounded),
// B [K,NB] row-major (already tf32). C stride NP (store unguarded: buffers
// padded so grid covers exactly). RESID: C = A*B + R (R stride NP).
template<bool RESID>
__global__ void __launch_bounds__(256) gemm_tf32(const float* __restrict__ A,
                                                 const float* __restrict__ B,
                                                 float* __restrict__ C,
                                                 const float* __restrict__ R,
                                                 int M, int NP, int NB, int K) {
    __shared__ float As[2][128][24];   // 16 used + pad (stride mult of 8)
    __shared__ float Bs[2][16][136];   // 128 used + pad

    int tid  = threadIdx.x;
    int warp = tid >> 5, wm = warp >> 1, wn = warp & 1;
    int row0 = blockIdx.y * 128, col0 = blockIdx.x * 128;

    wmma::fragment<wmma::accumulator, 16, 16, 8, float> acc[2][4];
    #pragma unroll
    for (int i = 0; i < 2; i++)
        #pragma unroll
        for (int j = 0; j < 4; j++) wmma::fill_fragment(acc[i][j], 0.f);

    auto issue_stage = [&](int s, int k0) {
        #pragma unroll
        for (int i = 0; i < 2; i++) {
            int idx = tid + 256 * i;
            int r = idx >> 2, c = (idx & 3) * 4;
            CP16(smem_u32(&As[s][r][c]), A + (size_t)(row0 + r) * K + k0 + c);
        }
        #pragma unroll
        for (int i = 0; i < 2; i++) {
            int idx = tid + 256 * i;
            int r = idx >> 5, c = (idx & 31) * 4;
            CP16(smem_u32(&Bs[s][r][c]), B + (size_t)(k0 + r) * NB + col0 + c);
        }
    };

    int nk = K / 16;
    issue_stage(0, 0);  CP_COMMIT();
    issue_stage(1, 16); CP_COMMIT();

    for (int i = 0; i < nk; i++) {
        int s = i & 1;
        if (i + 1 < nk) { CP_WAIT(1); } else { CP_WAIT(0); }
        __syncthreads();
        #pragma unroll
        for (int kk = 0; kk < 16; kk += 8) {
            wmma::fragment<wmma::matrix_a, 16, 16, 8, wmma::precision::tf32, wmma::row_major> af[2];
            wmma::fragment<wmma::matrix_b, 16, 16, 8, wmma::precision::tf32, wmma::row_major> bf[4];
            #pragma unroll
            for (int a = 0; a < 2; a++)
                wmma::load_matrix_sync(af[a], &As[s][wm * 32 + a * 16][kk], 24);
            #pragma unroll
            for (int b = 0; b < 4; b++)
                wmma::load_matrix_sync(bf[b], &Bs[s][kk][wn * 64 + b * 16], 136);
            #pragma unroll
            for (int a = 0; a < 2; a++)
                #pragma unroll
                for (int b = 0; b < 4; b++)
                    wmma::mma_sync(acc[a][b], af[a], bf[b], acc[a][b]);
        }
        __syncthreads();
        if (i + 2 < nk) { issue_stage(s, (i + 2) * 16); CP_COMMIT(); }
    }

    #pragma unroll
    for (int i = 0; i < 2; i++)
        #pragma unroll
        for (int j = 0; j < 4; j++) {
            int r = row0 + wm * 32 + i * 16;
            int c = col0 + wn * 64 + j * 16;
            float* Cp = C + (size_t)r * NP + c;
            if (RESID) {
                wmma::fragment<wmma::accumulator, 16, 16, 8, float> rf;
                wmma::load_matrix_sync(rf, R + (size_t)r * NP + c, NP, wmma::mem_row_major);
                #pragma unroll
                for (int e = 0; e < rf.num_elements; e++) acc[i][j].x[e] += rf.x[e];
            }
            wmma::store_matrix_sync(Cp, acc[i][j], NP, wmma::mem_row_major);
        }
}

// ---------------- 3) causal depthwise conv (K=4) + SiLU ---------------------
__global__ void conv_kernel(const float* __restrict__ cw, const float* __restrict__ cb) {
    int id = blockIdx.x * blockDim.x + threadIdx.x;
    if (id >= NBT * CONVCH) return;
    int c  = id % CONVCH;
    int bt = id / CONVCH;
    int t  = bt % LSEQ;
    int b  = bt / LSEQ;
    const float* src = g_zx + (size_t)(b * LSEQ) * DPROJP + DINNER + c;
    float acc = cb[c];
    #pragma unroll
    for (int k = 0; k < 4; k++) {
        int ti = t - 3 + k;
        if (ti >= 0) acc = fmaf(cw[c * 4 + k], src[(size_t)ti * DPROJP], acc);
    }
    g_xbc[id] = acc / (1.f + expf(-acc));   // SiLU
}

// ---------------- 4) dt softplus + dA ---------------------------------------
__global__ void dt_kernel(const float* __restrict__ dt_bias, const float* __restrict__ A_log) {
    int id = blockIdx.x * blockDim.x + threadIdx.x;
    if (id >= NBT * NHEADS) return;
    int h  = id % NHEADS;
    int bt = id / NHEADS;
    float v  = g_zx[(size_t)bt * DPROJP + (DINNER + DINNER + 2 * DSTATE) + h] + dt_bias[h];
    float sp = (v > 20.f) ? v : log1pf(expf(v));
    g_dt[id] = sp;
    g_dA[id] = expf(-expf(A_log[h]) * sp);
}

// ---------------- 5) selective scan: smem-staged chunks + f32x2 -------------
// One block per (b,h). 512 threads: p = tid/8 (head row), sub = tid%8 → 16
// states (as 8 packed f32x2) per thread. Per chunk, B/C/x/dA/dt for TCH steps
// are loaded cooperatively (coalesced) into smem; the inner loop reads them
// via broadcast LDS, eliminating the x64-redundant global loads.
__global__ void __launch_bounds__(512) scan_kernel(const float* __restrict__ Dv) {
    __shared__ float sBC[TCH][256];  // [t][0..127]=B, [128..255]=C
    __shared__ float sX [TCH][64];
    __shared__ float sdA[TCH];
    __shared__ float sdt[TCH];

    int blk = blockIdx.x;
    int b = blk / NHEADS, h = blk % NHEADS;
    int tid = threadIdx.x;
    int p = tid >> 3, sub = tid & 7, n0 = sub * 16;

    const float* base = g_xbc + (size_t)(b * LSEQ) * CONVCH;
    const float* dAb  = g_dA + (b * LSEQ) * NHEADS + h;
    const float* dtb  = g_dt + (b * LSEQ) * NHEADS + h;
    float Dh = Dv[h];
    float* yb = g_y + (size_t)(b * LSEQ) * DINNER + h * HEADDIM + p;

    u64 hs[8];
    #pragma unroll
    for (int i = 0; i < 8; i++) hs[i] = 0ull;

    for (int t0 = 0; t0 < LSEQ; t0 += TCH) {
        __syncthreads();
        // B/C: 32 rows x 256 floats = 2048 float4, 4 per thread
        #pragma unroll
        for (int i = 0; i < 4; i++) {
            int idx = tid + 512 * i;
            int r = idx >> 6, c = (idx & 63) * 4;
            *(float4*)&sBC[r][c] =
                *(const float4*)(base + (size_t)(t0 + r) * CONVCH + DINNER + c);
        }
        // x: 32 rows x 64 floats = 512 float4, 1 per thread
        {
            int r = tid >> 4, c = (tid & 15) * 4;
            *(float4*)&sX[r][c] =
                *(const float4*)(base + (size_t)(t0 + r) * CONVCH + h * HEADDIM + c);
        }
        if (tid < TCH)            sdA[tid]       = dAb[(t0 + tid) * NHEADS];
        else if (tid < 2 * TCH)   sdt[tid - TCH] = dtb[(t0 + tid - TCH) * NHEADS];
        __syncthreads();

        for (int tt = 0; tt < TCH; tt++) {
            float cdA = sdA[tt], cdt = sdt[tt], cx = sX[tt][p];
            float dtx = cdt * cx;
            u64 cdA2 = pk2(cdA, cdA);
            u64 dtx2 = pk2(dtx, dtx);
            u64 acc2 = 0ull;
            #pragma unroll
            for (int i = 0; i < 4; i++) {
                float4 bv = *(const float4*)&sBC[tt][n0 + i * 4];
                float4 cv = *(const float4*)&sBC[tt][128 + n0 + i * 4];
                u64 b01 = pk2(bv.x, bv.y), b23 = pk2(bv.z, bv.w);
                u64 c01 = pk2(cv.x, cv.y), c23 = pk2(cv.z, cv.w);
                hs[i*2]   = ffma2(cdA2, hs[i*2],   fmul2(dtx2, b01));
                acc2      = ffma2(hs[i*2],   c01, acc2);
                hs[i*2+1] = ffma2(cdA2, hs[i*2+1], fmul2(dtx2, b23));
                acc2      = ffma2(hs[i*2+1], c23, acc2);
            }
            float ax, ay; up2(acc2, ax, ay);
            float acc = ax + ay;
            acc += __shfl_down_sync(0xffffffffu, acc, 4, 8);
            acc += __shfl_down_sync(0xffffffffu, acc, 2, 8);
            acc += __shfl_down_sync(0xffffffffu, acc, 1, 8);
            if (sub == 0) yb[(size_t)(t0 + tt) * DINNER] = acc + Dh * cx;
        }
    }
}

// ---------------- 6) gate (y * silu(z)) + RMSNorm (emits tf32) ---------------
__global__ void __launch_bounds__(256) gate_kernel(const float* __restrict__ norm_w) {
    __shared__ float red[32];
    int row = blockIdx.x;
    const float* zr = g_zx + (size_t)row * DPROJP;   // z = first 1536 cols
    float* yr = g_y + (size_t)row * DINNER;
    float g[6], ss = 0.f;
    #pragma unroll
    for (int i = 0; i < 6; i++) {
        int c = threadIdx.x + i * 256;
        float z = zr[c];
        float y = yr[c];
        float gv = y * (z / (1.f + expf(-z)));
        g[i] = gv;
        ss += gv * gv;
    }
    float tot = block_reduce_sum(ss, red);
    float inv = rsqrtf(tot / DINNER + EPSV);
    #pragma unroll
    for (int i = 0; i < 6; i++) {
        int c = threadIdx.x + i * 256;
        yr[c] = to_tf32(g[i] * inv * norm_w[c]);
    }
}

// ---------------- launcher ---------------------------------------------------
extern "C" void kernel_launch(void* const* d_in, const int* in_sizes, int n_in,
                              void* d_out, int out_size) {
    const float* x       = (const float*)d_in[0];
    const float* ln_w    = (const float*)d_in[1];
    const float* ln_b    = (const float*)d_in[2];
    const float* W_in    = (const float*)d_in[3];
    const float* conv_w  = (const float*)d_in[4];
    const float* conv_b  = (const float*)d_in[5];
    const float* A_log   = (const float*)d_in[6];
    const float* Dv      = (const float*)d_in[7];
    const float* dt_bias = (const float*)d_in[8];
    const float* norm_w  = (const float*)d_in[9];
    const float* W_out   = (const float*)d_in[10];
    float* out = (float*)d_out;

    float *pu, *pzx, *py, *pwin, *pwout;
    cudaGetSymbolAddress((void**)&pu,    g_u);
    cudaGetSymbolAddress((void**)&pzx,   g_zx);
    cudaGetSymbolAddress((void**)&py,    g_y);
    cudaGetSymbolAddress((void**)&pwin,  g_win);
    cudaGetSymbolAddress((void**)&pwout, g_wout);

    cvt_win_kernel <<<(DMODEL * DPROJP + 255) / 256, 256>>>(W_in);
    cvt_wout_kernel<<<(DINNER * DMODEL + 255) / 256, 256>>>(W_out);

    ln_kernel<<<NBT, 256>>>(x, ln_w, ln_b);

    // GEMM1: [16384x768] @ [768x3456(tf32,padded)] -> g_zx [16384x3456]
    dim3 g1(DPROJP / 128, NBT / 128);   // 27 x 128
    gemm_tf32<false><<<g1, 256>>>(pu, pwin, pzx, nullptr,
                                  NBT, DPROJP, DPROJP, DMODEL);

    conv_kernel<<<(NBT * CONVCH + 255) / 256, 256>>>(conv_w, conv_b);
    dt_kernel<<<(NBT * NHEADS + 255) / 256, 256>>>(dt_bias, A_log);

    scan_kernel<<<BSZ * NHEADS, 512>>>(Dv);

    gate_kernel<<<NBT, 256>>>(norm_w);

    // GEMM2: [16384x1536] @ [1536x768] + x -> out [16384x768]
    dim3 g2(DMODEL / 128, NBT / 128);   // 6 x 128
    gemm_tf32<true><<<g2, 256>>>(py, pwout, out, x,
                                 NBT, DMODEL, DMODEL, DINNER);
}